// round 11
// baseline (speedup 1.0000x reference)
#include <cuda_runtime.h>
#include <cuda_bf16.h>
#include <cstdint>
#include <cstring>

#define N_NODES 100000
#define N_EDGES 1600000
#define IN_DIM  512
#define HID_DIM 64
#define NSB ((N_NODES + 1023) / 1024)   // 98 scan blocks

#define PB 148                           // persistent blocks (single wave)
#define PT 1024
#define PSTRIDE (PB * PT)

typedef unsigned long long u64;
#define DC_ONE_CNT (((u64)1) << 48)
#define DC_SCALE   1099511627776.0f     // 2^40
#define DC_INV     (1.0f / 1099511627776.0f)
#define DC_MASK    0xFFFFFFFFFFFFULL

// ---------------- scratch (static device globals: allocation-free) ----------
__device__ int   g_idx64;
__device__ int   g_bar;                  // grid-barrier counter (reset by init)
__device__ u64   g_dc[N_NODES];          // packed: cnt<<48 | fixed-point deg
__device__ float g_dinv[N_NODES];
__device__ int   g_rs[N_NODES + 1];
__device__ int   g_cur[N_NODES];
__device__ int   g_bsum[NSB];
__device__ int   g_boff[NSB];
__device__ int   g_src[N_EDGES];
__device__ float g_w[N_EDGES];
__device__ float g_h[(size_t)N_NODES * HID_DIM];   // GEMM output (both layers)
__device__ float g_h2[(size_t)N_NODES * HID_DIM];  // layer-1 agg output
// bf16 hi/lo split of W, stored [n][k] (B operand)
__device__ __nv_bfloat16 g_b1hi[64 * IN_DIM];
__device__ __nv_bfloat16 g_b1lo[64 * IN_DIM];
__device__ __nv_bfloat16 g_b2hi[64 * HID_DIM];
__device__ __nv_bfloat16 g_b2lo[64 * HID_DIM];

// ---------------- helpers -----------------------------------------------------
__device__ __forceinline__ void mma_bf16(float* c, const uint32_t* a,
                                         uint32_t b0, uint32_t b1) {
    asm("mma.sync.aligned.m16n8k16.row.col.f32.bf16.bf16.f32 "
        "{%0,%1,%2,%3},{%4,%5,%6,%7},{%8,%9},{%0,%1,%2,%3};"
        : "+f"(c[0]), "+f"(c[1]), "+f"(c[2]), "+f"(c[3])
        : "r"(a[0]), "r"(a[1]), "r"(a[2]), "r"(a[3]), "r"(b0), "r"(b1));
}
__device__ __forceinline__ int load_idx(const void* ei, long long pos) {
    if (g_idx64) return (int)((const long long*)ei)[pos];
    return ((const int*)ei)[pos];
}
__device__ __forceinline__ uint32_t bf2u(__nv_bfloat162 t) {
    uint32_t u; memcpy(&u, &t, 4); return u;
}

// grid barrier: all PB blocks resident (single wave), monotonic counter.
__device__ __forceinline__ void gsync(int phase) {
    __syncthreads();
    if (threadIdx.x == 0) {
        __threadfence();
        atomicAdd(&g_bar, 1);
        while (*(volatile int*)&g_bar < phase * PB) {}
        __threadfence();
    }
    __syncthreads();
}

// ---------------- init: deg/cnt + dtype detect + W split + bar reset ---------
__global__ void init_kernel(const int* __restrict__ ei32,
                            const float* __restrict__ W1,
                            const float* __restrict__ W2) {
    int i = blockIdx.x * blockDim.x + threadIdx.x;
    if (i == 0) g_bar = 0;
    // self-loop: count 1, weight 1.0 (fixed-point 2^40)
    if (i < N_NODES) g_dc[i] = DC_ONE_CNT + (u64)(1.0f * DC_SCALE);
    if (blockIdx.x == 0 && threadIdx.x < 32) {
        int nz = 0;
#pragma unroll
        for (int j = 0; j < 4; j++) nz |= ei32[1 + 2 * (threadIdx.x * 4 + j)];
        unsigned b = __ballot_sync(0xffffffffu, nz != 0);
        if (threadIdx.x == 0) g_idx64 = (b == 0u) ? 1 : 0;
    }
    if (i < IN_DIM * 64) {
        int k = i / 64, n = i % 64;
        float w = W1[i];
        __nv_bfloat16 h = __float2bfloat16(w);
        g_b1hi[n * IN_DIM + k] = h;
        g_b1lo[n * IN_DIM + k] = __float2bfloat16(w - __bfloat162float(h));
    }
    if (i < HID_DIM * 64) {
        int k = i / 64, n = i % 64;
        float w = W2[i];
        __nv_bfloat16 h = __float2bfloat16(w);
        g_b2hi[n * HID_DIM + k] = h;
        g_b2lo[n * HID_DIM + k] = __float2bfloat16(w - __bfloat162float(h));
    }
}

// ---------------- persistent preprocessing: hist+scan+slack+reorder ----------
__global__ void __launch_bounds__(PT) prep_kernel(const void* __restrict__ ei,
                                                  const float* __restrict__ ew) {
    __shared__ int ws[32];
    __shared__ int ws2[4];
    int tid = threadIdx.x, blk = blockIdx.x;
    int lane = tid & 31, wrp = tid >> 5;
    int gt = blk * PT + tid;

    // ---- phase 0: degree histogram (one packed u64 atomic per edge) ----
    for (int e = gt; e < N_EDGES; e += PSTRIDE) {
        int d = load_idx(ei, (long long)N_EDGES + e);
        if ((unsigned)d < (unsigned)N_NODES) {
            u64 p = DC_ONE_CNT + (u64)(ew[e] * DC_SCALE);
            atomicAdd(&g_dc[d], p);
        }
    }
    gsync(1);

    // ---- phase 1: block-local scan of counts + dinv ----
    {
        u64 p = (gt < N_NODES) ? g_dc[gt] : 0ULL;
        if (gt < N_NODES) {
            float deg = (float)(p & DC_MASK) * DC_INV;
            g_dinv[gt] = (deg > 0.0f) ? rsqrtf(deg) : 0.0f;
        }
        int v = (int)(p >> 48);
        int x = v;
#pragma unroll
        for (int off = 1; off < 32; off <<= 1) {
            int y = __shfl_up_sync(0xffffffffu, x, off);
            if (lane >= off) x += y;
        }
        if (lane == 31) ws[wrp] = x;
        __syncthreads();
        if (wrp == 0) {
            int s = ws[lane];
#pragma unroll
            for (int off = 1; off < 32; off <<= 1) {
                int y = __shfl_up_sync(0xffffffffu, s, off);
                if (lane >= off) s += y;
            }
            ws[lane] = s;
        }
        __syncthreads();
        int incl = x + (wrp > 0 ? ws[wrp - 1] : 0);
        if (gt < N_NODES) g_rs[gt] = incl - v;          // block-local exclusive
        if (tid == PT - 1 && blk < NSB) g_bsum[blk] = incl;
    }
    gsync(2);

    // ---- phase 2: scan of block sums (block 0 only) ----
    if (blk == 0) {
        int v = (tid < NSB) ? g_bsum[tid] : 0;
        int x = v;
#pragma unroll
        for (int off = 1; off < 32; off <<= 1) {
            int y = __shfl_up_sync(0xffffffffu, x, off);
            if (lane >= off) x += y;
        }
        if (lane == 31 && wrp < 4) ws2[wrp] = x;
        __syncthreads();
        if (tid == 0) {
            int a = 0;
            for (int j = 0; j < 4; j++) { int t2 = ws2[j]; ws2[j] = a; a += t2; }
        }
        __syncthreads();
        if (tid < 128) {
            int excl = x - v + ws2[wrp];
            if (tid < NSB) g_boff[tid] = excl;
            if (tid == NSB - 1) g_rs[N_NODES] = excl + v;
        }
    }
    gsync(3);

    // ---- phase 3: add block offsets ----
    if (gt < N_NODES) {
        int r = g_rs[gt] + g_boff[blk];
        g_rs[gt] = r;
        g_cur[gt] = r;
    }
    gsync(4);

    // ---- phase 4: slack-zero (disjoint slots) + reorder ----
    if (gt < N_NODES) {
        int e2 = g_rs[gt + 1] - 1;   // per-node slack slot (from self-loop count)
        g_src[e2] = 0;
        g_w[e2] = 0.0f;
    }
    for (int e = gt; e < N_EDGES; e += PSTRIDE) {
        int s = load_idx(ei, e);
        int d = load_idx(ei, (long long)N_EDGES + e);
        if ((unsigned)d >= (unsigned)N_NODES) continue;
        int p = atomicAdd(&g_cur[d], 1);
        if ((unsigned)s < (unsigned)N_NODES) {
            g_src[p] = s;
            g_w[p]   = g_dinv[s] * ew[e] * g_dinv[d];
        } else {
            g_src[p] = 0;
            g_w[p]   = 0.0f;
        }
    }
}

// ---------------- GEMM: g_h[M,64] = X[M,K] @ W[K,64], bf16 3-pass -----------
// truncation hi/lo split of A: hi = bits&0xFFFF0000 (exact), lo = x - hi.
template <int K, bool FROM_G_H2>
__global__ void __launch_bounds__(128) mma_gemm_kernel(
    const float* __restrict__ Xext) {
    __shared__ uint32_t ash[128][20];
    __shared__ uint32_t asl[128][20];
    __shared__ uint32_t bsh[64][20];
    __shared__ uint32_t bsl[64][20];

    const float* X = FROM_G_H2 ? (const float*)g_h2 : Xext;
    const __nv_bfloat16* Bhi = (K == IN_DIM) ? g_b1hi : g_b2hi;
    const __nv_bfloat16* Blo = (K == IN_DIM) ? g_b1lo : g_b2lo;

    const int M = N_NODES;
    int t = threadIdx.x, wid = t >> 5, lane = t & 31;
    int g = lane >> 2, tig = lane & 3;
    int rowBase = blockIdx.x * 128;

    float acc[2][8][4] = {};

    for (int ch = 0; ch < K / 32; ch++) {
        int k0 = ch * 32;
        __syncthreads();
#pragma unroll
        for (int it = 0; it < 8; it++) {
            int id = t + it * 128;
            int row = id >> 3, q = id & 7;
            int gr = rowBase + row;
            float4 v = make_float4(0.f, 0.f, 0.f, 0.f);
            if (gr < M) v = *(const float4*)(X + (size_t)gr * K + k0 + q * 4);
            uint32_t xb = __float_as_uint(v.x), yb = __float_as_uint(v.y);
            uint32_t zb = __float_as_uint(v.z), wb = __float_as_uint(v.w);
            uint32_t h0 = __byte_perm(xb, yb, 0x7632);
            uint32_t h1 = __byte_perm(zb, wb, 0x7632);
            float lx = v.x - __uint_as_float(xb & 0xFFFF0000u);
            float ly = v.y - __uint_as_float(yb & 0xFFFF0000u);
            float lz = v.z - __uint_as_float(zb & 0xFFFF0000u);
            float lw = v.w - __uint_as_float(wb & 0xFFFF0000u);
            uint32_t l0 = bf2u(__floats2bfloat162_rn(lx, ly));
            uint32_t l1 = bf2u(__floats2bfloat162_rn(lz, lw));
            ash[row][q * 2] = h0; ash[row][q * 2 + 1] = h1;
            asl[row][q * 2] = l0; asl[row][q * 2 + 1] = l1;
        }
#pragma unroll
        for (int it = 0; it < 2; it++) {
            int id = t + it * 128;
            int n = id >> 2, u = id & 3;
            *(uint4*)&bsh[n][u * 4] = *(const uint4*)(Bhi + (size_t)n * K + k0 + u * 8);
            *(uint4*)&bsl[n][u * 4] = *(const uint4*)(Blo + (size_t)n * K + k0 + u * 8);
        }
        __syncthreads();

#pragma unroll
        for (int ks = 0; ks < 2; ks++) {
            int w0 = tig + 8 * ks, w1 = tig + 4 + 8 * ks;
            uint32_t ah[2][4], al[2][4];
#pragma unroll
            for (int mt = 0; mt < 2; mt++) {
                int r = wid * 32 + mt * 16 + g;
                ah[mt][0] = ash[r][w0];  ah[mt][1] = ash[r + 8][w0];
                ah[mt][2] = ash[r][w1];  ah[mt][3] = ash[r + 8][w1];
                al[mt][0] = asl[r][w0];  al[mt][1] = asl[r + 8][w0];
                al[mt][2] = asl[r][w1];  al[mt][3] = asl[r + 8][w1];
            }
#pragma unroll
            for (int nt = 0; nt < 8; nt++) {
                int n = nt * 8 + g;
                uint32_t bh0 = bsh[n][w0], bh1 = bsh[n][w1];
                uint32_t bl0 = bsl[n][w0], bl1 = bsl[n][w1];
#pragma unroll
                for (int mt = 0; mt < 2; mt++) {
                    mma_bf16(acc[mt][nt], ah[mt], bh0, bh1);
                    mma_bf16(acc[mt][nt], ah[mt], bl0, bl1);
                    mma_bf16(acc[mt][nt], al[mt], bh0, bh1);
                }
            }
        }
    }
#pragma unroll
    for (int mt = 0; mt < 2; mt++) {
        int r0g = rowBase + wid * 32 + mt * 16 + g;
#pragma unroll
        for (int nt = 0; nt < 8; nt++) {
            int col = nt * 8 + tig * 2;
            if (r0g < M)
                *(float2*)(g_h + (size_t)r0g * 64 + col) =
                    make_float2(acc[mt][nt][0], acc[mt][nt][1]);
            if (r0g + 8 < M)
                *(float2*)(g_h + (size_t)(r0g + 8) * 64 + col) =
                    make_float2(acc[mt][nt][2], acc[mt][nt][3]);
        }
    }
}

// ---------------- aggregation: warp per node, CSR gather, no atomics --------
template <bool RELU>
__global__ void __launch_bounds__(256) agg_kernel(
    const float* __restrict__ bias, float2* __restrict__ outp) {
    const float2* H = (const float2*)g_h;
    float2* out = RELU ? (float2*)g_h2 : outp;

    int gw   = (blockIdx.x * blockDim.x + threadIdx.x) >> 5;
    int lane = threadIdx.x & 31;
    if (gw >= N_NODES) return;
    int node = gw;

    float di = g_dinv[node];
    float sn = di * di;
    float2 hv = H[(size_t)node * 32 + lane];
    float ax = sn * hv.x, ay = sn * hv.y;

    int b = g_rs[node], en = g_rs[node + 1];
    for (int i = b; i < en; i += 32) {
        int rem = en - i;
        int src = 0; float w = 0.f;
        if (lane < rem) { src = g_src[i + lane]; w = g_w[i + lane]; }
        int m = rem < 32 ? rem : 32;
        int j = 0;
        for (; j + 4 <= m; j += 4) {
            int   s0 = __shfl_sync(0xffffffffu, src, j);
            int   s1 = __shfl_sync(0xffffffffu, src, j + 1);
            int   s2 = __shfl_sync(0xffffffffu, src, j + 2);
            int   s3 = __shfl_sync(0xffffffffu, src, j + 3);
            float w0 = __shfl_sync(0xffffffffu, w, j);
            float w1 = __shfl_sync(0xffffffffu, w, j + 1);
            float w2 = __shfl_sync(0xffffffffu, w, j + 2);
            float w3 = __shfl_sync(0xffffffffu, w, j + 3);
            float2 x0 = H[(size_t)s0 * 32 + lane];
            float2 x1 = H[(size_t)s1 * 32 + lane];
            float2 x2 = H[(size_t)s2 * 32 + lane];
            float2 x3 = H[(size_t)s3 * 32 + lane];
            ax += w0 * x0.x; ay += w0 * x0.y;
            ax += w1 * x1.x; ay += w1 * x1.y;
            ax += w2 * x2.x; ay += w2 * x2.y;
            ax += w3 * x3.x; ay += w3 * x3.y;
        }
        for (; j < m; j++) {
            int   s0 = __shfl_sync(0xffffffffu, src, j);
            float w0 = __shfl_sync(0xffffffffu, w, j);
            float2 x0 = H[(size_t)s0 * 32 + lane];
            ax += w0 * x0.x; ay += w0 * x0.y;
        }
    }
    float2 bb = ((const float2*)bias)[lane];
    ax += bb.x; ay += bb.y;
    if (RELU) { ax = fmaxf(ax, 0.f); ay = fmaxf(ay, 0.f); }
    out[(size_t)node * 32 + lane] = make_float2(ax, ay);
}

// ---------------- launch -----------------------------------------------------
extern "C" void kernel_launch(void* const* d_in, const int* in_sizes, int n_in,
                              void* d_out, int out_size) {
    const float* x   = (const float*)d_in[0];
    const void*  ei  = d_in[1];
    const float* ew  = (const float*)d_in[2];
    const float* W1  = (const float*)d_in[3];
    const float* b1  = (const float*)d_in[4];
    const float* W2  = (const float*)d_in[5];
    const float* b2  = (const float*)d_in[6];
    float*       out = (float*)d_out;

    const int TPB = 256;
    int nBlocksN = (N_NODES + TPB - 1) / TPB;
    int gemmBlocks = (N_NODES + 127) / 128;
    int aggBlocks  = (N_NODES + 7) / 8;

    // CSR build: init (+barrier reset) then ONE persistent kernel
    init_kernel<<<nBlocksN, TPB>>>((const int*)ei, W1, W2);
    prep_kernel<<<PB, PT>>>(ei, ew);

    // layer 1
    mma_gemm_kernel<IN_DIM, false><<<gemmBlocks, 128>>>(x);
    agg_kernel<true><<<aggBlocks, TPB>>>(b1, nullptr);

    // layer 2
    mma_gemm_kernel<HID_DIM, true><<<gemmBlocks, 128>>>(nullptr);
    agg_kernel<false><<<aggBlocks, TPB>>>(b2, (float2*)out);
}

// round 12
// speedup vs baseline: 1.0206x; 1.0206x over previous
#include <cuda_runtime.h>
#include <cuda_bf16.h>
#include <cstdint>
#include <cstring>

#define N_NODES 100000
#define N_EDGES 1600000
#define IN_DIM  512
#define HID_DIM 64
#define NSB ((N_NODES + 1023) / 1024)   // 98 scan blocks

typedef unsigned long long u64;
#define DC_ONE_CNT (((u64)1) << 48)
#define DC_SCALE   1099511627776.0f     // 2^40
#define DC_INV     (1.0f / 1099511627776.0f)
#define DC_MASK    0xFFFFFFFFFFFFULL

// ---------------- scratch (static device globals: allocation-free) ----------
__device__ int   g_idx64;
__device__ u64   g_dc[N_NODES];          // packed: cnt<<48 | fixed-point deg
__device__ float g_dinv[N_NODES];
__device__ int   g_rs[N_NODES + 1];
__device__ int   g_cur[N_NODES];
__device__ int   g_bsum[NSB];
__device__ int   g_boff[NSB];
__device__ int   g_src[N_EDGES];
__device__ float g_w[N_EDGES];
__device__ float g_h[(size_t)N_NODES * HID_DIM];   // GEMM output (both layers)
__device__ float g_h2[(size_t)N_NODES * HID_DIM];  // layer-1 agg output
// bf16 hi/lo split of W, stored [n][k] (B operand)
__device__ __nv_bfloat16 g_b1hi[64 * IN_DIM];
__device__ __nv_bfloat16 g_b1lo[64 * IN_DIM];
__device__ __nv_bfloat16 g_b2hi[64 * HID_DIM];
__device__ __nv_bfloat16 g_b2lo[64 * HID_DIM];

// ---------------- helpers -----------------------------------------------------
__device__ __forceinline__ void mma_bf16(float* c, const uint32_t* a,
                                         uint32_t b0, uint32_t b1) {
    asm("mma.sync.aligned.m16n8k16.row.col.f32.bf16.bf16.f32 "
        "{%0,%1,%2,%3},{%4,%5,%6,%7},{%8,%9},{%0,%1,%2,%3};"
        : "+f"(c[0]), "+f"(c[1]), "+f"(c[2]), "+f"(c[3])
        : "r"(a[0]), "r"(a[1]), "r"(a[2]), "r"(a[3]), "r"(b0), "r"(b1));
}
__device__ __forceinline__ int load_idx(const void* ei, long long pos) {
    if (g_idx64) return (int)((const long long*)ei)[pos];
    return ((const int*)ei)[pos];
}
__device__ __forceinline__ uint32_t bf2u(__nv_bfloat162 t) {
    uint32_t u; memcpy(&u, &t, 4); return u;
}

// ---------------- init: deg/cnt + dtype detect + W split ---------------------
__global__ void init_kernel(const int* __restrict__ ei32,
                            const float* __restrict__ W1,
                            const float* __restrict__ W2) {
    int i = blockIdx.x * blockDim.x + threadIdx.x;
    // self-loop: count 1, weight 1.0 (fixed-point 2^40)
    if (i < N_NODES) g_dc[i] = DC_ONE_CNT + (u64)(1.0f * DC_SCALE);
    if (blockIdx.x == 0 && threadIdx.x < 32) {
        int nz = 0;
#pragma unroll
        for (int j = 0; j < 4; j++) nz |= ei32[1 + 2 * (threadIdx.x * 4 + j)];
        unsigned b = __ballot_sync(0xffffffffu, nz != 0);
        if (threadIdx.x == 0) g_idx64 = (b == 0u) ? 1 : 0;
    }
    if (i < IN_DIM * 64) {
        int k = i / 64, n = i % 64;
        float w = W1[i];
        __nv_bfloat16 h = __float2bfloat16(w);
        g_b1hi[n * IN_DIM + k] = h;
        g_b1lo[n * IN_DIM + k] = __float2bfloat16(w - __bfloat162float(h));
    }
    if (i < HID_DIM * 64) {
        int k = i / 64, n = i % 64;
        float w = W2[i];
        __nv_bfloat16 h = __float2bfloat16(w);
        g_b2hi[n * HID_DIM + k] = h;
        g_b2lo[n * HID_DIM + k] = __float2bfloat16(w - __bfloat162float(h));
    }
}

// one packed 64-bit atomic per edge
__global__ void deg_hist_kernel(const void* __restrict__ ei,
                                const float* __restrict__ ew) {
    int e = blockIdx.x * blockDim.x + threadIdx.x;
    if (e >= N_EDGES) return;
    int d = load_idx(ei, (long long)N_EDGES + e);
    if ((unsigned)d < (unsigned)N_NODES) {
        u64 p = DC_ONE_CNT + (u64)(ew[e] * DC_SCALE);
        atomicAdd(&g_dc[d], p);
    }
}

// ---------------- scans (decode packed deg/cnt in scan1) ---------------------
__global__ void scan1_kernel() {
    __shared__ int ws[32];
    int b = blockIdx.x, tid = threadIdx.x, lane = tid & 31, wid = tid >> 5;
    int i = b * 1024 + tid;
    u64 p = (i < N_NODES) ? g_dc[i] : 0ULL;
    if (i < N_NODES) {
        float deg = (float)(p & DC_MASK) * DC_INV;
        g_dinv[i] = (deg > 0.0f) ? rsqrtf(deg) : 0.0f;
    }
    int v = (int)(p >> 48);
    int x = v;
#pragma unroll
    for (int off = 1; off < 32; off <<= 1) {
        int y = __shfl_up_sync(0xffffffffu, x, off);
        if (lane >= off) x += y;
    }
    if (lane == 31) ws[wid] = x;
    __syncthreads();
    if (wid == 0) {
        int s = ws[lane];
#pragma unroll
        for (int off = 1; off < 32; off <<= 1) {
            int y = __shfl_up_sync(0xffffffffu, s, off);
            if (lane >= off) s += y;
        }
        ws[lane] = s;
    }
    __syncthreads();
    int incl = x + (wid > 0 ? ws[wid - 1] : 0);
    if (i < N_NODES) g_rs[i] = incl - v;
    if (tid == 1023) g_bsum[b] = incl;
}

__global__ void scan2_kernel() {
    __shared__ int ws[4];
    int tid = threadIdx.x, lane = tid & 31, wid = tid >> 5;
    int v = (tid < NSB) ? g_bsum[tid] : 0;
    int x = v;
#pragma unroll
    for (int off = 1; off < 32; off <<= 1) {
        int y = __shfl_up_sync(0xffffffffu, x, off);
        if (lane >= off) x += y;
    }
    if (lane == 31) ws[wid] = x;
    __syncthreads();
    if (tid == 0) {
        int a = 0;
        for (int j = 0; j < 4; j++) { int t = ws[j]; ws[j] = a; a += t; }
    }
    __syncthreads();
    int excl = x - v + ws[wid];
    if (tid < NSB) g_boff[tid] = excl;
    if (tid == NSB - 1) g_rs[N_NODES] = excl + v;
}

__global__ void scan3_kernel() {
    int i = blockIdx.x * 1024 + threadIdx.x;
    if (i < N_NODES) {
        int r = g_rs[i] + g_boff[blockIdx.x];
        g_rs[i] = r;
        g_cur[i] = r;
    }
}

// zero the one never-written slack slot per node (count included self-loop)
__global__ void slack_kernel() {
    int node = blockIdx.x * blockDim.x + threadIdx.x;
    if (node >= N_NODES) return;
    int e = g_rs[node + 1] - 1;
    g_src[e] = 0;
    g_w[e] = 0.0f;
}

__global__ void reorder_kernel(const void* __restrict__ ei,
                               const float* __restrict__ ew) {
    int e = blockIdx.x * blockDim.x + threadIdx.x;
    if (e >= N_EDGES) return;
    int s = load_idx(ei, e);
    int d = load_idx(ei, (long long)N_EDGES + e);
    if ((unsigned)d >= (unsigned)N_NODES) return;
    int p = atomicAdd(&g_cur[d], 1);
    if ((unsigned)s < (unsigned)N_NODES) {
        g_src[p] = s;
        g_w[p]   = g_dinv[s] * ew[e] * g_dinv[d];
    } else {
        g_src[p] = 0;
        g_w[p]   = 0.0f;
    }
}

// ---------------- GEMM: g_h[M,64] = X[M,K] @ W[K,64], bf16 3-pass -----------
// truncation hi/lo split of A: hi = bits&0xFFFF0000 (exact), lo = x - hi.
template <int K, bool FROM_G_H2>
__global__ void __launch_bounds__(128) mma_gemm_kernel(
    const float* __restrict__ Xext) {
    __shared__ uint32_t ash[128][20];
    __shared__ uint32_t asl[128][20];
    __shared__ uint32_t bsh[64][20];
    __shared__ uint32_t bsl[64][20];

    const float* X = FROM_G_H2 ? (const float*)g_h2 : Xext;
    const __nv_bfloat16* Bhi = (K == IN_DIM) ? g_b1hi : g_b2hi;
    const __nv_bfloat16* Blo = (K == IN_DIM) ? g_b1lo : g_b2lo;

    const int M = N_NODES;
    int t = threadIdx.x, wid = t >> 5, lane = t & 31;
    int g = lane >> 2, tig = lane & 3;
    int rowBase = blockIdx.x * 128;

    float acc[2][8][4] = {};

    for (int ch = 0; ch < K / 32; ch++) {
        int k0 = ch * 32;
        __syncthreads();
#pragma unroll
        for (int it = 0; it < 8; it++) {
            int id = t + it * 128;
            int row = id >> 3, q = id & 7;
            int gr = rowBase + row;
            float4 v = make_float4(0.f, 0.f, 0.f, 0.f);
            if (gr < M) v = *(const float4*)(X + (size_t)gr * K + k0 + q * 4);
            uint32_t xb = __float_as_uint(v.x), yb = __float_as_uint(v.y);
            uint32_t zb = __float_as_uint(v.z), wb = __float_as_uint(v.w);
            uint32_t h0 = __byte_perm(xb, yb, 0x7632);
            uint32_t h1 = __byte_perm(zb, wb, 0x7632);
            float lx = v.x - __uint_as_float(xb & 0xFFFF0000u);
            float ly = v.y - __uint_as_float(yb & 0xFFFF0000u);
            float lz = v.z - __uint_as_float(zb & 0xFFFF0000u);
            float lw = v.w - __uint_as_float(wb & 0xFFFF0000u);
            uint32_t l0 = bf2u(__floats2bfloat162_rn(lx, ly));
            uint32_t l1 = bf2u(__floats2bfloat162_rn(lz, lw));
            ash[row][q * 2] = h0; ash[row][q * 2 + 1] = h1;
            asl[row][q * 2] = l0; asl[row][q * 2 + 1] = l1;
        }
#pragma unroll
        for (int it = 0; it < 2; it++) {
            int id = t + it * 128;
            int n = id >> 2, u = id & 3;
            *(uint4*)&bsh[n][u * 4] = *(const uint4*)(Bhi + (size_t)n * K + k0 + u * 8);
            *(uint4*)&bsl[n][u * 4] = *(const uint4*)(Blo + (size_t)n * K + k0 + u * 8);
        }
        __syncthreads();

#pragma unroll
        for (int ks = 0; ks < 2; ks++) {
            int w0 = tig + 8 * ks, w1 = tig + 4 + 8 * ks;
            uint32_t ah[2][4], al[2][4];
#pragma unroll
            for (int mt = 0; mt < 2; mt++) {
                int r = wid * 32 + mt * 16 + g;
                ah[mt][0] = ash[r][w0];  ah[mt][1] = ash[r + 8][w0];
                ah[mt][2] = ash[r][w1];  ah[mt][3] = ash[r + 8][w1];
                al[mt][0] = asl[r][w0];  al[mt][1] = asl[r + 8][w0];
                al[mt][2] = asl[r][w1];  al[mt][3] = asl[r + 8][w1];
            }
#pragma unroll
            for (int nt = 0; nt < 8; nt++) {
                int n = nt * 8 + g;
                uint32_t bh0 = bsh[n][w0], bh1 = bsh[n][w1];
                uint32_t bl0 = bsl[n][w0], bl1 = bsl[n][w1];
#pragma unroll
                for (int mt = 0; mt < 2; mt++) {
                    mma_bf16(acc[mt][nt], ah[mt], bh0, bh1);
                    mma_bf16(acc[mt][nt], ah[mt], bl0, bl1);
                    mma_bf16(acc[mt][nt], al[mt], bh0, bh1);
                }
            }
        }
    }
#pragma unroll
    for (int mt = 0; mt < 2; mt++) {
        int r0g = rowBase + wid * 32 + mt * 16 + g;
#pragma unroll
        for (int nt = 0; nt < 8; nt++) {
            int col = nt * 8 + tig * 2;
            if (r0g < M)
                *(float2*)(g_h + (size_t)r0g * 64 + col) =
                    make_float2(acc[mt][nt][0], acc[mt][nt][1]);
            if (r0g + 8 < M)
                *(float2*)(g_h + (size_t)(r0g + 8) * 64 + col) =
                    make_float2(acc[mt][nt][2], acc[mt][nt][3]);
        }
    }
}

// ---------------- aggregation: warp/node, 2 edges per step, float4 lanes ----
// lanes 0-15 gather edge e's row (float4 per lane), lanes 16-31 edge e+1.
// One variable-index shfl feeds each half its own src/w. Halves reduced by
// shfl_xor(16) at the end. Tail edges carry w=0 (harmless row-0 load).
template <bool RELU>
__global__ void __launch_bounds__(256) agg_kernel(
    const float* __restrict__ bias, float4* __restrict__ outp) {
    const float4* H = (const float4*)g_h;
    float4* out = RELU ? (float4*)g_h2 : outp;

    int gw   = (blockIdx.x * blockDim.x + threadIdx.x) >> 5;
    int lane = threadIdx.x & 31;
    if (gw >= N_NODES) return;
    int node = gw;
    int half = lane >> 4, li = lane & 15;

    float4 acc = make_float4(0.f, 0.f, 0.f, 0.f);

    int b = g_rs[node], en = g_rs[node + 1];
    for (int i = b; i < en; i += 32) {
        int rem = en - i;
        int src = 0; float w = 0.f;
        if (lane < rem) { src = g_src[i + lane]; w = g_w[i + lane]; }
        int m = rem < 32 ? rem : 32;
        int steps = (m + 1) >> 1;
        int j = 0;
        for (; j + 4 <= steps; j += 4) {
#pragma unroll
            for (int u = 0; u < 4; u++) {
                int sl = 2 * (j + u) + half;
                int   s  = __shfl_sync(0xffffffffu, src, sl);
                float wv = __shfl_sync(0xffffffffu, w, sl);
                float4 xv = H[(size_t)s * 16 + li];
                acc.x += wv * xv.x; acc.y += wv * xv.y;
                acc.z += wv * xv.z; acc.w += wv * xv.w;
            }
        }
        for (; j < steps; j++) {
            int sl = 2 * j + half;
            int   s  = __shfl_sync(0xffffffffu, src, sl);
            float wv = __shfl_sync(0xffffffffu, w, sl);
            float4 xv = H[(size_t)s * 16 + li];
            acc.x += wv * xv.x; acc.y += wv * xv.y;
            acc.z += wv * xv.z; acc.w += wv * xv.w;
        }
    }
    // combine halves
    acc.x += __shfl_xor_sync(0xffffffffu, acc.x, 16);
    acc.y += __shfl_xor_sync(0xffffffffu, acc.y, 16);
    acc.z += __shfl_xor_sync(0xffffffffu, acc.z, 16);
    acc.w += __shfl_xor_sync(0xffffffffu, acc.w, 16);

    if (half == 0) {
        float di = g_dinv[node];
        float sn = di * di;
        float4 own = H[(size_t)node * 16 + li];
        float4 bb  = ((const float4*)bias)[li];
        float rx = acc.x + sn * own.x + bb.x;
        float ry = acc.y + sn * own.y + bb.y;
        float rz = acc.z + sn * own.z + bb.z;
        float rw = acc.w + sn * own.w + bb.w;
        if (RELU) {
            rx = fmaxf(rx, 0.f); ry = fmaxf(ry, 0.f);
            rz = fmaxf(rz, 0.f); rw = fmaxf(rw, 0.f);
        }
        out[(size_t)node * 16 + li] = make_float4(rx, ry, rz, rw);
    }
}

// ---------------- launch -----------------------------------------------------
extern "C" void kernel_launch(void* const* d_in, const int* in_sizes, int n_in,
                              void* d_out, int out_size) {
    const float* x   = (const float*)d_in[0];
    const void*  ei  = d_in[1];
    const float* ew  = (const float*)d_in[2];
    const float* W1  = (const float*)d_in[3];
    const float* b1  = (const float*)d_in[4];
    const float* W2  = (const float*)d_in[5];
    const float* b2  = (const float*)d_in[6];
    float*       out = (float*)d_out;

    const int TPB = 256;
    int nBlocksN = (N_NODES + TPB - 1) / TPB;
    int nBlocksE = (N_EDGES + TPB - 1) / TPB;
    int gemmBlocks = (N_NODES + 127) / 128;
    int aggBlocks  = (N_NODES + 7) / 8;

    // CSR build (R10 structure — separate kernels)
    init_kernel<<<nBlocksN, TPB>>>((const int*)ei, W1, W2);
    deg_hist_kernel<<<nBlocksE, TPB>>>(ei, ew);
    scan1_kernel<<<NSB, 1024>>>();
    scan2_kernel<<<1, 128>>>();
    scan3_kernel<<<NSB, 1024>>>();
    slack_kernel<<<nBlocksN, TPB>>>();
    reorder_kernel<<<nBlocksE, TPB>>>(ei, ew);

    // layer 1
    mma_gemm_kernel<IN_DIM, false><<<gemmBlocks, 128>>>(x);
    agg_kernel<true><<<aggBlocks, TPB>>>(b1, nullptr);

    // layer 2
    mma_gemm_kernel<HID_DIM, true><<<gemmBlocks, 128>>>(nullptr);
    agg_kernel<false><<<aggBlocks, TPB>>>(b2, (float4*)out);
}

// round 13
// speedup vs baseline: 1.0345x; 1.0136x over previous
#include <cuda_runtime.h>
#include <cuda_bf16.h>
#include <cstdint>
#include <cstring>

#define N_NODES 100000
#define N_EDGES 1600000
#define IN_DIM  512
#define HID_DIM 64
#define NSB ((N_NODES + 1023) / 1024)   // 98 scan blocks

typedef unsigned long long u64;
typedef unsigned int u32;
#define DC_ONE_CNT (((u64)1) << 48)
#define DC_SCALE   1099511627776.0f     // 2^40
#define DC_INV     (1.0f / 1099511627776.0f)
#define DC_MASK    0xFFFFFFFFFFFFULL

// ---------------- scratch (static device globals: allocation-free) ----------
__device__ int   g_idx64;
__device__ u64   g_dc[N_NODES];          // packed: cnt<<48 | fixed-point deg
__device__ u64   g_sstate[NSB];          // lookback state: flag<<32 | value
__device__ float g_dinv[N_NODES];
__device__ int   g_rs[N_NODES + 1];
__device__ int   g_cur[N_NODES];
__device__ int   g_src[N_EDGES];
__device__ float g_w[N_EDGES];
__device__ float g_h[(size_t)N_NODES * HID_DIM];   // GEMM output (both layers)
__device__ float g_h2[(size_t)N_NODES * HID_DIM];  // layer-1 agg output
// bf16 hi/lo split of W, stored [n][k] (B operand)
__device__ __nv_bfloat16 g_b1hi[64 * IN_DIM];
__device__ __nv_bfloat16 g_b1lo[64 * IN_DIM];
__device__ __nv_bfloat16 g_b2hi[64 * HID_DIM];
__device__ __nv_bfloat16 g_b2lo[64 * HID_DIM];

// ---------------- helpers -----------------------------------------------------
__device__ __forceinline__ void mma_bf16(float* c, const uint32_t* a,
                                         uint32_t b0, uint32_t b1) {
    asm("mma.sync.aligned.m16n8k16.row.col.f32.bf16.bf16.f32 "
        "{%0,%1,%2,%3},{%4,%5,%6,%7},{%8,%9},{%0,%1,%2,%3};"
        : "+f"(c[0]), "+f"(c[1]), "+f"(c[2]), "+f"(c[3])
        : "r"(a[0]), "r"(a[1]), "r"(a[2]), "r"(a[3]), "r"(b0), "r"(b1));
}
__device__ __forceinline__ int load_idx(const void* ei, long long pos) {
    if (g_idx64) return (int)((const long long*)ei)[pos];
    return ((const int*)ei)[pos];
}
__device__ __forceinline__ uint32_t bf2u(__nv_bfloat162 t) {
    uint32_t u; memcpy(&u, &t, 4); return u;
}

// ---------------- init: deg/cnt + scan state + dtype detect + W split --------
__global__ void init_kernel(const int* __restrict__ ei32,
                            const float* __restrict__ W1,
                            const float* __restrict__ W2) {
    int i = blockIdx.x * blockDim.x + threadIdx.x;
    // self-loop weight 1.0 in deg; cnt = 0 (self-loop NOT a CSR slot)
    if (i < N_NODES) g_dc[i] = (u64)(1.0f * DC_SCALE);
    if (i < NSB) g_sstate[i] = 0ULL;
    if (blockIdx.x == 0 && threadIdx.x < 32) {
        int nz = 0;
#pragma unroll
        for (int j = 0; j < 4; j++) nz |= ei32[1 + 2 * (threadIdx.x * 4 + j)];
        unsigned b = __ballot_sync(0xffffffffu, nz != 0);
        if (threadIdx.x == 0) g_idx64 = (b == 0u) ? 1 : 0;
    }
    if (i < IN_DIM * 64) {
        int k = i / 64, n = i % 64;
        float w = W1[i];
        __nv_bfloat16 h = __float2bfloat16(w);
        g_b1hi[n * IN_DIM + k] = h;
        g_b1lo[n * IN_DIM + k] = __float2bfloat16(w - __bfloat162float(h));
    }
    if (i < HID_DIM * 64) {
        int k = i / 64, n = i % 64;
        float w = W2[i];
        __nv_bfloat16 h = __float2bfloat16(w);
        g_b2hi[n * HID_DIM + k] = h;
        g_b2lo[n * HID_DIM + k] = __float2bfloat16(w - __bfloat162float(h));
    }
}

// one packed 64-bit atomic per edge
__global__ void deg_hist_kernel(const void* __restrict__ ei,
                                const float* __restrict__ ew) {
    int e = blockIdx.x * blockDim.x + threadIdx.x;
    if (e >= N_EDGES) return;
    int d = load_idx(ei, (long long)N_EDGES + e);
    if ((unsigned)d < (unsigned)N_NODES) {
        u64 p = DC_ONE_CNT + (u64)(ew[e] * DC_SCALE);
        atomicAdd(&g_dc[d], p);
    }
}

// ---------------- single-pass decoupled-lookback scan + dinv -----------------
// 98 blocks x 1024 threads, all resident in wave 1 (in-order) => no deadlock.
__global__ void __launch_bounds__(1024) scan_kernel() {
    __shared__ int ws[32];
    __shared__ int s_excl;
    int b = blockIdx.x, tid = threadIdx.x, lane = tid & 31, wid = tid >> 5;
    int i = b * 1024 + tid;

    u64 p = (i < N_NODES) ? g_dc[i] : 0ULL;
    if (i < N_NODES) {
        float deg = (float)(p & DC_MASK) * DC_INV;
        g_dinv[i] = (deg > 0.0f) ? rsqrtf(deg) : 0.0f;
    }
    int v = (int)(p >> 48);
    int x = v;
#pragma unroll
    for (int off = 1; off < 32; off <<= 1) {
        int y = __shfl_up_sync(0xffffffffu, x, off);
        if (lane >= off) x += y;
    }
    if (lane == 31) ws[wid] = x;
    __syncthreads();
    if (wid == 0) {
        int s = ws[lane];
#pragma unroll
        for (int off = 1; off < 32; off <<= 1) {
            int y = __shfl_up_sync(0xffffffffu, s, off);
            if (lane >= off) s += y;
        }
        ws[lane] = s;
    }
    __syncthreads();
    int incl = x + (wid > 0 ? ws[wid - 1] : 0);     // block-local inclusive

    // publish aggregate ASAP (not for block 0 — it publishes prefix directly)
    if (tid == 1023 && b > 0)
        atomicExch(&g_sstate[b], (1ULL << 32) | (u32)incl);

    // lookback (thread 0)
    if (tid == 0) {
        int excl = 0;
        int pb = b - 1;
        while (pb >= 0) {
            u64 st = atomicAdd(&g_sstate[pb], 0ULL);
            u32 f = (u32)(st >> 32);
            if (f == 0u) continue;        // spin
            excl += (int)(u32)st;
            if (f == 2u) break;           // found inclusive prefix
            pb--;
        }
        s_excl = excl;
    }
    __syncthreads();
    int excl = s_excl;

    // publish inclusive prefix (upgrades/sets flag=2)
    if (tid == 1023)
        atomicExch(&g_sstate[b], (2ULL << 32) | (u32)(excl + incl));

    if (i < N_NODES) {
        int r = excl + incl - v;          // global exclusive
        g_rs[i] = r;
        g_cur[i] = r;
    }
    if (b == NSB - 1 && tid == 1023) g_rs[N_NODES] = excl + incl;
}

__global__ void reorder_kernel(const void* __restrict__ ei,
                               const float* __restrict__ ew) {
    int e = blockIdx.x * blockDim.x + threadIdx.x;
    if (e >= N_EDGES) return;
    int s = load_idx(ei, e);
    int d = load_idx(ei, (long long)N_EDGES + e);
    if ((unsigned)d >= (unsigned)N_NODES) return;
    int p = atomicAdd(&g_cur[d], 1);
    if ((unsigned)s < (unsigned)N_NODES) {
        g_src[p] = s;
        g_w[p]   = g_dinv[s] * ew[e] * g_dinv[d];
    } else {
        g_src[p] = 0;
        g_w[p]   = 0.0f;
    }
}

// ---------------- GEMM: g_h[M,64] = X[M,K] @ W[K,64], bf16 3-pass -----------
// truncation hi/lo split of A: hi = bits&0xFFFF0000 (exact), lo = x - hi.
template <int K, bool FROM_G_H2>
__global__ void __launch_bounds__(128) mma_gemm_kernel(
    const float* __restrict__ Xext) {
    __shared__ uint32_t ash[128][20];
    __shared__ uint32_t asl[128][20];
    __shared__ uint32_t bsh[64][20];
    __shared__ uint32_t bsl[64][20];

    const float* X = FROM_G_H2 ? (const float*)g_h2 : Xext;
    const __nv_bfloat16* Bhi = (K == IN_DIM) ? g_b1hi : g_b2hi;
    const __nv_bfloat16* Blo = (K == IN_DIM) ? g_b1lo : g_b2lo;

    const int M = N_NODES;
    int t = threadIdx.x, wid = t >> 5, lane = t & 31;
    int g = lane >> 2, tig = lane & 3;
    int rowBase = blockIdx.x * 128;

    float acc[2][8][4] = {};

    for (int ch = 0; ch < K / 32; ch++) {
        int k0 = ch * 32;
        __syncthreads();
#pragma unroll
        for (int it = 0; it < 8; it++) {
            int id = t + it * 128;
            int row = id >> 3, q = id & 7;
            int gr = rowBase + row;
            float4 v = make_float4(0.f, 0.f, 0.f, 0.f);
            if (gr < M) v = *(const float4*)(X + (size_t)gr * K + k0 + q * 4);
            uint32_t xb = __float_as_uint(v.x), yb = __float_as_uint(v.y);
            uint32_t zb = __float_as_uint(v.z), wb = __float_as_uint(v.w);
            uint32_t h0 = __byte_perm(xb, yb, 0x7632);
            uint32_t h1 = __byte_perm(zb, wb, 0x7632);
            float lx = v.x - __uint_as_float(xb & 0xFFFF0000u);
            float ly = v.y - __uint_as_float(yb & 0xFFFF0000u);
            float lz = v.z - __uint_as_float(zb & 0xFFFF0000u);
            float lw = v.w - __uint_as_float(wb & 0xFFFF0000u);
            uint32_t l0 = bf2u(__floats2bfloat162_rn(lx, ly));
            uint32_t l1 = bf2u(__floats2bfloat162_rn(lz, lw));
            ash[row][q * 2] = h0; ash[row][q * 2 + 1] = h1;
            asl[row][q * 2] = l0; asl[row][q * 2 + 1] = l1;
        }
#pragma unroll
        for (int it = 0; it < 2; it++) {
            int id = t + it * 128;
            int n = id >> 2, u = id & 3;
            *(uint4*)&bsh[n][u * 4] = *(const uint4*)(Bhi + (size_t)n * K + k0 + u * 8);
            *(uint4*)&bsl[n][u * 4] = *(const uint4*)(Blo + (size_t)n * K + k0 + u * 8);
        }
        __syncthreads();

#pragma unroll
        for (int ks = 0; ks < 2; ks++) {
            int w0 = tig + 8 * ks, w1 = tig + 4 + 8 * ks;
            uint32_t ah[2][4], al[2][4];
#pragma unroll
            for (int mt = 0; mt < 2; mt++) {
                int r = wid * 32 + mt * 16 + g;
                ah[mt][0] = ash[r][w0];  ah[mt][1] = ash[r + 8][w0];
                ah[mt][2] = ash[r][w1];  ah[mt][3] = ash[r + 8][w1];
                al[mt][0] = asl[r][w0];  al[mt][1] = asl[r + 8][w0];
                al[mt][2] = asl[r][w1];  al[mt][3] = asl[r + 8][w1];
            }
#pragma unroll
            for (int nt = 0; nt < 8; nt++) {
                int n = nt * 8 + g;
                uint32_t bh0 = bsh[n][w0], bh1 = bsh[n][w1];
                uint32_t bl0 = bsl[n][w0], bl1 = bsl[n][w1];
#pragma unroll
                for (int mt = 0; mt < 2; mt++) {
                    mma_bf16(acc[mt][nt], ah[mt], bh0, bh1);
                    mma_bf16(acc[mt][nt], ah[mt], bl0, bl1);
                    mma_bf16(acc[mt][nt], al[mt], bh0, bh1);
                }
            }
        }
    }
#pragma unroll
    for (int mt = 0; mt < 2; mt++) {
        int r0g = rowBase + wid * 32 + mt * 16 + g;
#pragma unroll
        for (int nt = 0; nt < 8; nt++) {
            int col = nt * 8 + tig * 2;
            if (r0g < M)
                *(float2*)(g_h + (size_t)r0g * 64 + col) =
                    make_float2(acc[mt][nt][0], acc[mt][nt][1]);
            if (r0g + 8 < M)
                *(float2*)(g_h + (size_t)(r0g + 8) * 64 + col) =
                    make_float2(acc[mt][nt][2], acc[mt][nt][3]);
        }
    }
}

// ---------------- aggregation: warp per node, CSR gather, no atomics --------
template <bool RELU>
__global__ void __launch_bounds__(256) agg_kernel(
    const float* __restrict__ bias, float2* __restrict__ outp) {
    const float2* H = (const float2*)g_h;
    float2* out = RELU ? (float2*)g_h2 : outp;

    int gw   = (blockIdx.x * blockDim.x + threadIdx.x) >> 5;
    int lane = threadIdx.x & 31;
    if (gw >= N_NODES) return;
    int node = gw;

    float di = g_dinv[node];
    float sn = di * di;
    float2 hv = H[(size_t)node * 32 + lane];
    float ax = sn * hv.x, ay = sn * hv.y;

    int b = g_rs[node], en = g_rs[node + 1];
    for (int i = b; i < en; i += 32) {
        int rem = en - i;
        int src = 0; float w = 0.f;
        if (lane < rem) { src = g_src[i + lane]; w = g_w[i + lane]; }
        int m = rem < 32 ? rem : 32;
        int j = 0;
        for (; j + 4 <= m; j += 4) {
            int   s0 = __shfl_sync(0xffffffffu, src, j);
            int   s1 = __shfl_sync(0xffffffffu, src, j + 1);
            int   s2 = __shfl_sync(0xffffffffu, src, j + 2);
            int   s3 = __shfl_sync(0xffffffffu, src, j + 3);
            float w0 = __shfl_sync(0xffffffffu, w, j);
            float w1 = __shfl_sync(0xffffffffu, w, j + 1);
            float w2 = __shfl_sync(0xffffffffu, w, j + 2);
            float w3 = __shfl_sync(0xffffffffu, w, j + 3);
            float2 x0 = H[(size_t)s0 * 32 + lane];
            float2 x1 = H[(size_t)s1 * 32 + lane];
            float2 x2 = H[(size_t)s2 * 32 + lane];
            float2 x3 = H[(size_t)s3 * 32 + lane];
            ax += w0 * x0.x; ay += w0 * x0.y;
            ax += w1 * x1.x; ay += w1 * x1.y;
            ax += w2 * x2.x; ay += w2 * x2.y;
            ax += w3 * x3.x; ay += w3 * x3.y;
        }
        for (; j < m; j++) {
            int   s0 = __shfl_sync(0xffffffffu, src, j);
            float w0 = __shfl_sync(0xffffffffu, w, j);
            float2 x0 = H[(size_t)s0 * 32 + lane];
            ax += w0 * x0.x; ay += w0 * x0.y;
        }
    }
    float2 bb = ((const float2*)bias)[lane];
    ax += bb.x; ay += bb.y;
    if (RELU) { ax = fmaxf(ax, 0.f); ay = fmaxf(ay, 0.f); }
    out[(size_t)node * 32 + lane] = make_float2(ax, ay);
}

// ---------------- launch -----------------------------------------------------
extern "C" void kernel_launch(void* const* d_in, const int* in_sizes, int n_in,
                              void* d_out, int out_size) {
    const float* x   = (const float*)d_in[0];
    const void*  ei  = d_in[1];
    const float* ew  = (const float*)d_in[2];
    const float* W1  = (const float*)d_in[3];
    const float* b1  = (const float*)d_in[4];
    const float* W2  = (const float*)d_in[5];
    const float* b2  = (const float*)d_in[6];
    float*       out = (float*)d_out;

    const int TPB = 256;
    int nBlocksN = (N_NODES + TPB - 1) / TPB;
    int nBlocksE = (N_EDGES + TPB - 1) / TPB;
    int gemmBlocks = (N_NODES + 127) / 128;
    int aggBlocks  = (N_NODES + 7) / 8;

    // 8 launches total; gemm1 is launch #4 (gets the ncu profile slot)
    init_kernel<<<nBlocksN, TPB>>>((const int*)ei, W1, W2);
    deg_hist_kernel<<<nBlocksE, TPB>>>(ei, ew);
    scan_kernel<<<NSB, 1024>>>();
    mma_gemm_kernel<IN_DIM, false><<<gemmBlocks, 128>>>(x);
    reorder_kernel<<<nBlocksE, TPB>>>(ei, ew);

    agg_kernel<true><<<aggBlocks, TPB>>>(b1, nullptr);
    mma_gemm_kernel<HID_DIM, true><<<gemmBlocks, 128>>>(nullptr);
    agg_kernel<false><<<aggBlocks, TPB>>>(b2, (float2*)out);
}

// round 14
// speedup vs baseline: 1.0995x; 1.0629x over previous
#include <cuda_runtime.h>
#include <cuda_bf16.h>
#include <cstdint>
#include <cstring>

#define N_NODES 100000
#define N_EDGES 1600000
#define IN_DIM  512
#define HID_DIM 64
#define NSB ((N_NODES + 1023) / 1024)   // 98 scan blocks

typedef unsigned long long u64;
typedef unsigned int u32;
#define DC_ONE_CNT (((u64)1) << 48)
#define DC_SCALE   1099511627776.0f     // 2^40
#define DC_INV     (1.0f / 1099511627776.0f)
#define DC_MASK    0xFFFFFFFFFFFFULL

// ---------------- scratch (static device globals: allocation-free) ----------
__device__ int   g_idx64;
__device__ u64   g_dc[N_NODES];          // packed: cnt<<48 | fixed-point deg
__device__ u64   g_sstate[NSB];          // lookback state: flag<<32 | value
__device__ float g_dinv[N_NODES];
__device__ int   g_rs[N_NODES + 1];
__device__ int   g_cur[N_NODES];
__device__ int   g_src[N_EDGES];
__device__ float g_w[N_EDGES];
__device__ float g_h[(size_t)N_NODES * HID_DIM];   // GEMM output (both layers)
__device__ float g_h2[(size_t)N_NODES * HID_DIM];  // layer-1 agg output
// bf16 hi/lo split of W, stored [n][k] (B operand)
__device__ __nv_bfloat16 g_b1hi[64 * IN_DIM];
__device__ __nv_bfloat16 g_b1lo[64 * IN_DIM];
__device__ __nv_bfloat16 g_b2hi[64 * HID_DIM];
__device__ __nv_bfloat16 g_b2lo[64 * HID_DIM];

// ---------------- helpers -----------------------------------------------------
__device__ __forceinline__ void mma_bf16(float* c, const uint32_t* a,
                                         uint32_t b0, uint32_t b1) {
    asm("mma.sync.aligned.m16n8k16.row.col.f32.bf16.bf16.f32 "
        "{%0,%1,%2,%3},{%4,%5,%6,%7},{%8,%9},{%0,%1,%2,%3};"
        : "+f"(c[0]), "+f"(c[1]), "+f"(c[2]), "+f"(c[3])
        : "r"(a[0]), "r"(a[1]), "r"(a[2]), "r"(a[3]), "r"(b0), "r"(b1));
}
__device__ __forceinline__ int load_idx(const void* ei, long long pos) {
    if (g_idx64) return (int)((const long long*)ei)[pos];
    return ((const int*)ei)[pos];
}
__device__ __forceinline__ uint32_t bf2u(__nv_bfloat162 t) {
    uint32_t u; memcpy(&u, &t, 4); return u;
}

// ---------------- init: deg/cnt + scan state + dtype detect + W split --------
__global__ void init_kernel(const int* __restrict__ ei32,
                            const float* __restrict__ W1,
                            const float* __restrict__ W2) {
    int i = blockIdx.x * blockDim.x + threadIdx.x;
    // self-loop weight 1.0 in deg; cnt = 0 (self-loop NOT a CSR slot)
    if (i < N_NODES) g_dc[i] = (u64)(1.0f * DC_SCALE);
    if (i < NSB) g_sstate[i] = 0ULL;
    if (blockIdx.x == 0 && threadIdx.x < 32) {
        int nz = 0;
#pragma unroll
        for (int j = 0; j < 4; j++) nz |= ei32[1 + 2 * (threadIdx.x * 4 + j)];
        unsigned b = __ballot_sync(0xffffffffu, nz != 0);
        if (threadIdx.x == 0) g_idx64 = (b == 0u) ? 1 : 0;
    }
    if (i < IN_DIM * 64) {
        int k = i / 64, n = i % 64;
        float w = W1[i];
        __nv_bfloat16 h = __float2bfloat16(w);
        g_b1hi[n * IN_DIM + k] = h;
        g_b1lo[n * IN_DIM + k] = __float2bfloat16(w - __bfloat162float(h));
    }
    if (i < HID_DIM * 64) {
        int k = i / 64, n = i % 64;
        float w = W2[i];
        __nv_bfloat16 h = __float2bfloat16(w);
        g_b2hi[n * HID_DIM + k] = h;
        g_b2lo[n * HID_DIM + k] = __float2bfloat16(w - __bfloat162float(h));
    }
}

// one packed 64-bit atomic per edge
__global__ void deg_hist_kernel(const void* __restrict__ ei,
                                const float* __restrict__ ew) {
    int e = blockIdx.x * blockDim.x + threadIdx.x;
    if (e >= N_EDGES) return;
    int d = load_idx(ei, (long long)N_EDGES + e);
    if ((unsigned)d < (unsigned)N_NODES) {
        u64 p = DC_ONE_CNT + (u64)(ew[e] * DC_SCALE);
        atomicAdd(&g_dc[d], p);
    }
}

// ---------------- single-pass decoupled-lookback scan + dinv -----------------
__global__ void __launch_bounds__(1024) scan_kernel() {
    __shared__ int ws[32];
    __shared__ int s_excl;
    int b = blockIdx.x, tid = threadIdx.x, lane = tid & 31, wid = tid >> 5;
    int i = b * 1024 + tid;

    u64 p = (i < N_NODES) ? g_dc[i] : 0ULL;
    if (i < N_NODES) {
        float deg = (float)(p & DC_MASK) * DC_INV;
        g_dinv[i] = (deg > 0.0f) ? rsqrtf(deg) : 0.0f;
    }
    int v = (int)(p >> 48);
    int x = v;
#pragma unroll
    for (int off = 1; off < 32; off <<= 1) {
        int y = __shfl_up_sync(0xffffffffu, x, off);
        if (lane >= off) x += y;
    }
    if (lane == 31) ws[wid] = x;
    __syncthreads();
    if (wid == 0) {
        int s = ws[lane];
#pragma unroll
        for (int off = 1; off < 32; off <<= 1) {
            int y = __shfl_up_sync(0xffffffffu, s, off);
            if (lane >= off) s += y;
        }
        ws[lane] = s;
    }
    __syncthreads();
    int incl = x + (wid > 0 ? ws[wid - 1] : 0);

    if (tid == 1023 && b > 0)
        atomicExch(&g_sstate[b], (1ULL << 32) | (u32)incl);

    if (tid == 0) {
        int excl = 0;
        int pb = b - 1;
        while (pb >= 0) {
            u64 st = atomicAdd(&g_sstate[pb], 0ULL);
            u32 f = (u32)(st >> 32);
            if (f == 0u) continue;
            excl += (int)(u32)st;
            if (f == 2u) break;
            pb--;
        }
        s_excl = excl;
    }
    __syncthreads();
    int excl = s_excl;

    if (tid == 1023)
        atomicExch(&g_sstate[b], (2ULL << 32) | (u32)(excl + incl));

    if (i < N_NODES) {
        int r = excl + incl - v;
        g_rs[i] = r;
        g_cur[i] = r;
    }
    if (b == NSB - 1 && tid == 1023) g_rs[N_NODES] = excl + incl;
}

__global__ void reorder_kernel(const void* __restrict__ ei,
                               const float* __restrict__ ew) {
    int e = blockIdx.x * blockDim.x + threadIdx.x;
    if (e >= N_EDGES) return;
    int s = load_idx(ei, e);
    int d = load_idx(ei, (long long)N_EDGES + e);
    if ((unsigned)d >= (unsigned)N_NODES) return;
    int p = atomicAdd(&g_cur[d], 1);
    if ((unsigned)s < (unsigned)N_NODES) {
        g_src[p] = s;
        g_w[p]   = g_dinv[s] * ew[e] * g_dinv[d];
    } else {
        g_src[p] = 0;
        g_w[p]   = 0.0f;
    }
}

// ---------------- GEMM: g_h[M,64] = X[M,K] @ W[K,64], bf16 3-pass -----------
// 256 threads (8 warps). Warp tile 16 rows x 64 cols. K chunked by 32.
// Register-prefetch double-buffering: next chunk's LDGs issued before the MMA
// phase, convert+store after. Truncation hi/lo split of A.
template <int K, bool FROM_G_H2>
__global__ void __launch_bounds__(256) mma_gemm_kernel(
    const float* __restrict__ Xext) {
    __shared__ uint32_t ash[128][20];
    __shared__ uint32_t asl[128][20];
    __shared__ uint32_t bsh[64][20];
    __shared__ uint32_t bsl[64][20];

    const float* X = FROM_G_H2 ? (const float*)g_h2 : Xext;
    const __nv_bfloat16* Bhi = (K == IN_DIM) ? g_b1hi : g_b2hi;
    const __nv_bfloat16* Blo = (K == IN_DIM) ? g_b1lo : g_b2lo;

    const int M = N_NODES;
    constexpr int CH = K / 32;
    int t = threadIdx.x, wid = t >> 5, lane = t & 31;
    int g = lane >> 2, tig = lane & 3;
    int rowBase = blockIdx.x * 128;

    // per-thread load slots: A 4x float4, B 1x uint4 hi + 1x uint4 lo
    int arow[4], aq[4];
#pragma unroll
    for (int it = 0; it < 4; it++) {
        int id = t + it * 256;
        arow[it] = id >> 3;
        aq[it]   = id & 7;
    }
    int bn = t >> 2, bu = t & 3;

    float4 av[4];
    uint4 bvh, bvl;

    // prologue: load chunk 0
#pragma unroll
    for (int it = 0; it < 4; it++) {
        int gr = rowBase + arow[it];
        av[it] = (gr < M) ? *(const float4*)(X + (size_t)gr * K + aq[it] * 4)
                          : make_float4(0.f, 0.f, 0.f, 0.f);
    }
    bvh = *(const uint4*)(Bhi + (size_t)bn * K + bu * 8);
    bvl = *(const uint4*)(Blo + (size_t)bn * K + bu * 8);

    float acc[8][4] = {};

    for (int ch = 0; ch < CH; ch++) {
        // convert + store current regs to smem
#pragma unroll
        for (int it = 0; it < 4; it++) {
            float4 v = av[it];
            uint32_t xb = __float_as_uint(v.x), yb = __float_as_uint(v.y);
            uint32_t zb = __float_as_uint(v.z), wb = __float_as_uint(v.w);
            uint32_t h0 = __byte_perm(xb, yb, 0x7632);
            uint32_t h1 = __byte_perm(zb, wb, 0x7632);
            float lx = v.x - __uint_as_float(xb & 0xFFFF0000u);
            float ly = v.y - __uint_as_float(yb & 0xFFFF0000u);
            float lz = v.z - __uint_as_float(zb & 0xFFFF0000u);
            float lw = v.w - __uint_as_float(wb & 0xFFFF0000u);
            uint32_t l0 = bf2u(__floats2bfloat162_rn(lx, ly));
            uint32_t l1 = bf2u(__floats2bfloat162_rn(lz, lw));
            ash[arow[it]][aq[it] * 2]     = h0;
            ash[arow[it]][aq[it] * 2 + 1] = h1;
            asl[arow[it]][aq[it] * 2]     = l0;
            asl[arow[it]][aq[it] * 2 + 1] = l1;
        }
        *(uint4*)&bsh[bn][bu * 4] = bvh;
        *(uint4*)&bsl[bn][bu * 4] = bvl;
        __syncthreads();

        // prefetch next chunk into regs (LDGs fly during the MMA phase)
        if (ch + 1 < CH) {
            int k0n = (ch + 1) * 32;
#pragma unroll
            for (int it = 0; it < 4; it++) {
                int gr = rowBase + arow[it];
                av[it] = (gr < M)
                    ? *(const float4*)(X + (size_t)gr * K + k0n + aq[it] * 4)
                    : make_float4(0.f, 0.f, 0.f, 0.f);
            }
            bvh = *(const uint4*)(Bhi + (size_t)bn * K + k0n + bu * 8);
            bvl = *(const uint4*)(Blo + (size_t)bn * K + k0n + bu * 8);
        }

        // MMA phase on current smem tile
        int r = wid * 16 + g;
#pragma unroll
        for (int ks = 0; ks < 2; ks++) {
            int w0 = tig + 8 * ks, w1 = tig + 4 + 8 * ks;
            uint32_t ah[4], al[4];
            ah[0] = ash[r][w0];  ah[1] = ash[r + 8][w0];
            ah[2] = ash[r][w1];  ah[3] = ash[r + 8][w1];
            al[0] = asl[r][w0];  al[1] = asl[r + 8][w0];
            al[2] = asl[r][w1];  al[3] = asl[r + 8][w1];
#pragma unroll
            for (int nt = 0; nt < 8; nt++) {
                int n = nt * 8 + g;
                uint32_t bh0 = bsh[n][w0], bh1 = bsh[n][w1];
                uint32_t bl0 = bsl[n][w0], bl1 = bsl[n][w1];
                mma_bf16(acc[nt], ah, bh0, bh1);
                mma_bf16(acc[nt], ah, bl0, bl1);
                mma_bf16(acc[nt], al, bh0, bh1);
            }
        }
        __syncthreads();
    }

    // epilogue: warp covers rows wid*16+g (+8), cols nt*8 + tig*2
    int r0g = rowBase + wid * 16 + g;
#pragma unroll
    for (int nt = 0; nt < 8; nt++) {
        int col = nt * 8 + tig * 2;
        if (r0g < M)
            *(float2*)(g_h + (size_t)r0g * 64 + col) =
                make_float2(acc[nt][0], acc[nt][1]);
        if (r0g + 8 < M)
            *(float2*)(g_h + (size_t)(r0g + 8) * 64 + col) =
                make_float2(acc[nt][2], acc[nt][3]);
    }
}

// ---------------- aggregation: warp per node, CSR gather, no atomics --------
template <bool RELU>
__global__ void __launch_bounds__(256) agg_kernel(
    const float* __restrict__ bias, float2* __restrict__ outp) {
    const float2* H = (const float2*)g_h;
    float2* out = RELU ? (float2*)g_h2 : outp;

    int gw   = (blockIdx.x * blockDim.x + threadIdx.x) >> 5;
    int lane = threadIdx.x & 31;
    if (gw >= N_NODES) return;
    int node = gw;

    float di = g_dinv[node];
    float sn = di * di;
    float2 hv = H[(size_t)node * 32 + lane];
    float ax = sn * hv.x, ay = sn * hv.y;

    int b = g_rs[node], en = g_rs[node + 1];
    for (int i = b; i < en; i += 32) {
        int rem = en - i;
        int src = 0; float w = 0.f;
        if (lane < rem) { src = g_src[i + lane]; w = g_w[i + lane]; }
        int m = rem < 32 ? rem : 32;
        int j = 0;
        for (; j + 4 <= m; j += 4) {
            int   s0 = __shfl_sync(0xffffffffu, src, j);
            int   s1 = __shfl_sync(0xffffffffu, src, j + 1);
            int   s2 = __shfl_sync(0xffffffffu, src, j + 2);
            int   s3 = __shfl_sync(0xffffffffu, src, j + 3);
            float w0 = __shfl_sync(0xffffffffu, w, j);
            float w1 = __shfl_sync(0xffffffffu, w, j + 1);
            float w2 = __shfl_sync(0xffffffffu, w, j + 2);
            float w3 = __shfl_sync(0xffffffffu, w, j + 3);
            float2 x0 = H[(size_t)s0 * 32 + lane];
            float2 x1 = H[(size_t)s1 * 32 + lane];
            float2 x2 = H[(size_t)s2 * 32 + lane];
            float2 x3 = H[(size_t)s3 * 32 + lane];
            ax += w0 * x0.x; ay += w0 * x0.y;
            ax += w1 * x1.x; ay += w1 * x1.y;
            ax += w2 * x2.x; ay += w2 * x2.y;
            ax += w3 * x3.x; ay += w3 * x3.y;
        }
        for (; j < m; j++) {
            int   s0 = __shfl_sync(0xffffffffu, src, j);
            float w0 = __shfl_sync(0xffffffffu, w, j);
            float2 x0 = H[(size_t)s0 * 32 + lane];
            ax += w0 * x0.x; ay += w0 * x0.y;
        }
    }
    float2 bb = ((const float2*)bias)[lane];
    ax += bb.x; ay += bb.y;
    if (RELU) { ax = fmaxf(ax, 0.f); ay = fmaxf(ay, 0.f); }
    out[(size_t)node * 32 + lane] = make_float2(ax, ay);
}

// ---------------- launch -----------------------------------------------------
extern "C" void kernel_launch(void* const* d_in, const int* in_sizes, int n_in,
                              void* d_out, int out_size) {
    const float* x   = (const float*)d_in[0];
    const void*  ei  = d_in[1];
    const float* ew  = (const float*)d_in[2];
    const float* W1  = (const float*)d_in[3];
    const float* b1  = (const float*)d_in[4];
    const float* W2  = (const float*)d_in[5];
    const float* b2  = (const float*)d_in[6];
    float*       out = (float*)d_out;

    const int TPB = 256;
    int nBlocksN = (N_NODES + TPB - 1) / TPB;
    int nBlocksE = (N_EDGES + TPB - 1) / TPB;
    int gemmBlocks = (N_NODES + 127) / 128;
    int aggBlocks  = (N_NODES + 7) / 8;

    init_kernel<<<nBlocksN, TPB>>>((const int*)ei, W1, W2);
    deg_hist_kernel<<<nBlocksE, TPB>>>(ei, ew);
    scan_kernel<<<NSB, 1024>>>();
    mma_gemm_kernel<IN_DIM, false><<<gemmBlocks, 256>>>(x);   // launch #4: profiled
    reorder_kernel<<<nBlocksE, TPB>>>(ei, ew);

    agg_kernel<true><<<aggBlocks, TPB>>>(b1, nullptr);
    mma_gemm_kernel<HID_DIM, true><<<gemmBlocks, 256>>>(nullptr);
    agg_kernel<false><<<aggBlocks, TPB>>>(b2, (float2*)out);
}